// round 2
// baseline (speedup 1.0000x reference)
#include <cuda_runtime.h>

#define N_PRIORS   400000
#define N_CLASSES  81
#define K_CAND     1000
#define CAP        2048
#define IOU_THR    0.5f
#define SCORE_THR  0.3f

// ---------------- scratch (static device globals; no allocation) ----------------
__device__ unsigned            g_keys[N_PRIORS];      // float bits of best score (monotone for >=0)
__device__ unsigned char       g_labels[N_PRIORS];    // argmax over classes 1..80 (0..79)
__device__ unsigned long long  g_cand[CAP];           // (key<<32) | (0xFFFFFFFF - prior_idx)
__device__ unsigned            g_sup[K_CAND * 32];    // suppression bitmask rows (j>i only)
__device__ float g_cx1[1024], g_cy1[1024], g_cx2[1024], g_cy2[1024], g_cscore[1024];
__device__ int   g_clabel[1024];

struct RState {
  unsigned hist[4][256];
  unsigned done[4];
  unsigned prefix;
  unsigned k;
  unsigned kth;
  unsigned count;
};
__device__ RState g_state;

// ---------------- per-prior max/argmax over classes 1..80 (warp per prior) ----------------
// Block 0 also zeroes the radix state (consumed only by later kernels).
__global__ void k_reduce(const float* __restrict__ scores) {
  if (blockIdx.x == 0) {
    int t = threadIdx.x;
    unsigned* h = &g_state.hist[0][0];
    for (int i = t; i < 4 * 256; i += blockDim.x) h[i] = 0u;
    if (t < 4) g_state.done[t] = 0u;
    if (t == 0) g_state.count = 0u;
  }
  int lane  = threadIdx.x & 31;
  int warp  = (blockIdx.x * blockDim.x + threadIdx.x) >> 5;
  int nwarp = (gridDim.x * blockDim.x) >> 5;
  for (int p = warp; p < N_PRIORS; p += nwarp) {
    const float* row = scores + (size_t)p * N_CLASSES;
    float v0 = row[1 + lane];                        // sliced idx lane
    float v1 = row[33 + lane];                       // sliced idx 32+lane
    float v2 = (lane < 16) ? row[65 + lane] : 0.0f;  // sliced idx 64+lane
    unsigned long long m0 = ((unsigned long long)__float_as_uint(v0) << 32) | (0xFFFFFFFFu - (unsigned)lane);
    unsigned long long m1 = ((unsigned long long)__float_as_uint(v1) << 32) | (0xFFFFFFFFu - (unsigned)(32 + lane));
    unsigned long long m2 = (lane < 16)
        ? (((unsigned long long)__float_as_uint(v2) << 32) | (0xFFFFFFFFu - (unsigned)(64 + lane)))
        : 0ull;
    unsigned long long m = m0 > m1 ? m0 : m1;
    if (m2 > m) m = m2;
#pragma unroll
    for (int off = 16; off > 0; off >>= 1) {
      unsigned long long o = __shfl_xor_sync(0xFFFFFFFFu, m, off);
      if (o > m) m = o;
    }
    if (lane == 0) {
      g_keys[p]   = (unsigned)(m >> 32);
      g_labels[p] = (unsigned char)(~(unsigned)m);   // 0xFFFFFFFF - low = idx
    }
  }
}

// ---------------- radix-select round R (8 bits), warp-aggregated hist + fused scan ----------------
template <int R>
__global__ void k_radix() {
  __shared__ unsigned h[256];
  __shared__ unsigned s_prefix;
  __shared__ int s_last;
  if (threadIdx.x < 256) h[threadIdx.x] = 0u;
  if (threadIdx.x == 0) s_prefix = (R == 0) ? 0u : g_state.prefix;
  __syncthreads();
  unsigned prefix = s_prefix;
  const int SHIFT = 24 - 8 * R;
  int lane = threadIdx.x & 31;
  int stride = gridDim.x * blockDim.x;
  for (int i = blockIdx.x * blockDim.x + threadIdx.x; i < N_PRIORS; i += stride) {
    unsigned key = g_keys[i];
    bool match;
    if constexpr (R == 0) match = true;
    else                  match = ((key >> (SHIFT + 8)) == prefix);
    // warp-aggregated atomic: peers sharing a bin elect one leader
    unsigned bin = match ? ((key >> SHIFT) & 255u) : 0xFFFFFFFFu;
    unsigned peers = __match_any_sync(0xFFFFFFFFu, bin);
    int leader = __ffs(peers) - 1;
    if (lane == leader && bin != 0xFFFFFFFFu)
      atomicAdd(&h[bin], (unsigned)__popc(peers));
  }
  __syncthreads();
  if (threadIdx.x < 256) {
    unsigned c = h[threadIdx.x];
    if (c) atomicAdd(&g_state.hist[R][threadIdx.x], c);
  }
  __threadfence();
  if (threadIdx.x == 0)
    s_last = (atomicAdd(&g_state.done[R], 1u) == gridDim.x - 1) ? 1 : 0;
  __syncthreads();
  if (!s_last) return;
  if (threadIdx.x < 256) h[threadIdx.x] = g_state.hist[R][threadIdx.x];
  __syncthreads();
  if (threadIdx.x == 0) {
    unsigned k = (R == 0) ? (unsigned)K_CAND : g_state.k;
    int b = 255;
    for (; b > 0; b--) {
      unsigned c = h[b];
      if (k <= c) break;
      k -= c;
    }
    g_state.prefix = (prefix << 8) | (unsigned)b;
    g_state.k = k;
    if (R == 3) g_state.kth = (prefix << 8) | (unsigned)b;
  }
}

// ---------------- compact candidates with key >= kth ----------------
__global__ void k_compact() {
  unsigned kth = g_state.kth;
  int stride = gridDim.x * blockDim.x;
  for (int i = blockIdx.x * blockDim.x + threadIdx.x; i < N_PRIORS; i += stride) {
    unsigned key = g_keys[i];
    if (key >= kth) {
      unsigned pos = atomicAdd(&g_state.count, 1u);
      if (pos < CAP)
        g_cand[pos] = ((unsigned long long)key << 32) | (unsigned long long)(0xFFFFFFFFu - (unsigned)i);
    }
  }
}

// ---------------- single-block bitonic sort (2048) + gather candidate SoA ----------------
__global__ void k_sort(const float* __restrict__ boxes) {
  __shared__ unsigned long long s[CAP];
  __shared__ unsigned s_n;
  if (threadIdx.x == 0) s_n = min(g_state.count, (unsigned)CAP);
  __syncthreads();
  unsigned n = s_n;
  for (int t = threadIdx.x; t < CAP; t += blockDim.x)
    s[t] = (t < (int)n) ? g_cand[t] : 0ull;
  __syncthreads();
  for (int k = 2; k <= CAP; k <<= 1) {
    for (int j = k >> 1; j > 0; j >>= 1) {
      for (int idx = threadIdx.x; idx < CAP; idx += blockDim.x) {
        int l = idx ^ j;
        if (l > idx) {
          unsigned long long a = s[idx], b = s[l];
          bool up = ((idx & k) == 0);  // ascending network
          if ((a > b) == up) { s[idx] = b; s[l] = a; }
        }
      }
      __syncthreads();
    }
  }
  int t = threadIdx.x;
  if (t < K_CAND) {
    unsigned long long e = s[CAP - 1 - t];  // rank t descending
    unsigned key = (unsigned)(e >> 32);
    unsigned idx = 0xFFFFFFFFu - (unsigned)e;
    const float4* b4 = (const float4*)boxes;
    float4 bb = b4[idx];
    g_cx1[t] = bb.x; g_cy1[t] = bb.y; g_cx2[t] = bb.z; g_cy2[t] = bb.w;
    g_cscore[t] = __uint_as_float(key);
    g_clabel[t] = (int)g_labels[idx];
  }
}

// ---------------- grid kernel: suppression bitmask matrix (offset boxes, j > i) ----------------
__global__ void k_iou() {
  __shared__ float sx1[K_CAND], sy1[K_CAND], sx2[K_CAND], sy2[K_CAND], sar[K_CAND];
  for (int t = threadIdx.x; t < K_CAND; t += blockDim.x) {
    float off = (float)g_clabel[t] * 4.0f;
    float x1 = g_cx1[t] + off, y1 = g_cy1[t] + off;
    float x2 = g_cx2[t] + off, y2 = g_cy2[t] + off;
    sx1[t] = x1; sy1[t] = y1; sx2[t] = x2; sy2[t] = y2;
    sar[t] = (x2 - x1) * (y2 - y1);  // area from offset coords, like reference
  }
  __syncthreads();
  int g = blockIdx.x * blockDim.x + threadIdx.x;
  if (g >= K_CAND * 32) return;
  int i = g >> 5;
  int w = g & 31;
  float x1 = sx1[i], y1 = sy1[i], x2 = sx2[i], y2 = sy2[i], ai = sar[i];
  unsigned word = 0u;
#pragma unroll
  for (int jj = 0; jj < 32; jj++) {
    int j = w * 32 + jj;
    if (j > i && j < K_CAND) {
      float xx1 = fmaxf(x1, sx1[j]);
      float yy1 = fmaxf(y1, sy1[j]);
      float xx2 = fminf(x2, sx2[j]);
      float yy2 = fminf(y2, sy2[j]);
      float inter = fmaxf(xx2 - xx1, 0.0f) * fmaxf(yy2 - yy1, 0.0f);
      float uni = fmaxf(ai + sar[j] - inter, 1e-9f);
      float iou = __fdiv_rn(inter, uni);
      if (iou > IOU_THR) word |= (1u << jj);
    }
  }
  g_sup[i * 32 + w] = word;
}

// ---------------- final: sequential greedy reduction (1 warp) + output write ----------------
__global__ void k_final(float* __restrict__ out) {
  extern __shared__ unsigned ssup[];  // 32000 words = 128000 B
  __shared__ unsigned skeep[32];
  for (int t = threadIdx.x; t < K_CAND * 32; t += blockDim.x)
    ssup[t] = g_sup[t];
  __syncthreads();

  if (threadIdx.x < 32) {
    int lane = threadIdx.x;
    unsigned kw = 0u;  // keep word for columns [32*lane, 32*lane+32)
#pragma unroll
    for (int jj = 0; jj < 32; jj++) {
      int j = lane * 32 + jj;
      bool v = (j < K_CAND) && (g_cscore[j] > SCORE_THR);
      if (v) kw |= (1u << jj);
    }
    for (int c = 0; c < 32; c++) {
      unsigned bkw = __shfl_sync(0xFFFFFFFFu, kw, c);  // current chunk's keep word, replicated
      int base = c * 32;
#pragma unroll
      for (int r = 0; r < 32; r++) {
        int i = base + r;
        if (i < K_CAND) {
          unsigned rowl = ssup[i * 32 + lane];  // conflict-free
          unsigned rowc = ssup[i * 32 + c];     // broadcast
          if (bkw & (1u << r)) {
            kw  &= ~rowl;
            bkw &= ~rowc;
          }
        }
      }
    }
    skeep[lane] = kw;
  }
  __syncthreads();

  int t = threadIdx.x;
  if (t < K_CAND) {
    bool keep = (skeep[t >> 5] >> (t & 31)) & 1u;
    float kf = keep ? 1.0f : 0.0f;
    out[t * 4 + 0] = g_cx1[t] * kf;
    out[t * 4 + 1] = g_cy1[t] * kf;
    out[t * 4 + 2] = g_cx2[t] * kf;
    out[t * 4 + 3] = g_cy2[t] * kf;
    out[4000 + t] = keep ? (float)(g_clabel[t] + 1) : 0.0f;
    out[5000 + t] = g_cscore[t] * kf;
    out[6000 + t] = kf;
  }
}

// ---------------- launch ----------------
extern "C" void kernel_launch(void* const* d_in, const int* in_sizes, int n_in,
                              void* d_out, int out_size) {
  const float* scores = (const float*)d_in[0];
  const float* boxes  = (const float*)d_in[1];
  float* out = (float*)d_out;

  cudaFuncSetAttribute(k_final, cudaFuncAttributeMaxDynamicSharedMemorySize, 128000);

  k_reduce<<<2048, 256>>>(scores);
  k_radix<0><<<148, 256>>>();
  k_radix<1><<<148, 256>>>();
  k_radix<2><<<148, 256>>>();
  k_radix<3><<<148, 256>>>();
  k_compact<<<148, 256>>>();
  k_sort<<<1, 1024>>>(boxes);
  k_iou<<<125, 256>>>();
  k_final<<<1, 1024, 128000>>>(out);
}

// round 3
// speedup vs baseline: 1.0572x; 1.0572x over previous
#include <cuda_runtime.h>

#define N_PRIORS   400000
#define N4         (N_PRIORS / 4)
#define N_CLASSES  81
#define K_CAND     1000
#define CAP        2048
#define IOU_THR    0.5f
#define SCORE_THR  0.3f

// ---------------- scratch (static device globals; no allocation) ----------------
__device__ __align__(16) unsigned g_keys[N_PRIORS];  // float bits of best score
__device__ unsigned char       g_labels[N_PRIORS];   // argmax over classes 1..80 (0..79)
__device__ unsigned long long  g_cand[CAP];          // (key<<32) | (0xFFFFFFFF - prior_idx)
__device__ unsigned            g_sup[K_CAND * 32];   // suppression bitmask rows (j>i only)
__device__ float g_cx1[1024], g_cy1[1024], g_cx2[1024], g_cy2[1024], g_cscore[1024];
__device__ int   g_clabel[1024];

struct RState {
  unsigned hist[4][256];
  unsigned done[4];
  unsigned prefix;
  unsigned k;
  unsigned kth;
  unsigned count;
};
__device__ RState g_state;

// ---------------- per-prior max/argmax over classes 1..80 (warp per prior) ----------------
// Block 0 also zeroes the radix state (consumed only by later kernels).
__global__ void k_reduce(const float* __restrict__ scores) {
  if (blockIdx.x == 0) {
    int t = threadIdx.x;
    unsigned* h = &g_state.hist[0][0];
    for (int i = t; i < 4 * 256; i += blockDim.x) h[i] = 0u;
    if (t < 4) g_state.done[t] = 0u;
    if (t == 0) g_state.count = 0u;
  }
  int lane  = threadIdx.x & 31;
  int warp  = (blockIdx.x * blockDim.x + threadIdx.x) >> 5;
  int nwarp = (gridDim.x * blockDim.x) >> 5;
  for (int p = warp; p < N_PRIORS; p += nwarp) {
    const float* row = scores + (size_t)p * N_CLASSES;
    // streaming loads: don't let 130MB of scores evict the key array from L2
    float v0 = __ldcs(row + 1 + lane);                           // cls idx lane
    float v1 = __ldcs(row + 33 + lane);                          // cls idx 32+lane
    float v2 = (lane < 16) ? __ldcs(row + 65 + lane) : -1.0f;    // cls idx 64+lane
    float vmax = fmaxf(fmaxf(v0, v1), v2);
#pragma unroll
    for (int off = 16; off > 0; off >>= 1)
      vmax = fmaxf(vmax, __shfl_xor_sync(0xFFFFFFFFu, vmax, off));
    // first (lowest) class index achieving vmax — matches argmax semantics
    unsigned b0 = __ballot_sync(0xFFFFFFFFu, v0 == vmax);
    unsigned b1 = __ballot_sync(0xFFFFFFFFu, v1 == vmax);
    unsigned b2 = __ballot_sync(0xFFFFFFFFu, (lane < 16) && (v2 == vmax));
    if (lane == 0) {
      int idx = b0 ? (__ffs(b0) - 1)
                   : (b1 ? (32 + __ffs(b1) - 1) : (64 + __ffs(b2) - 1));
      g_keys[p]   = __float_as_uint(vmax);   // scores >= 0 -> bits are order-preserving
      g_labels[p] = (unsigned char)idx;
    }
  }
}

// ---------------- radix-select round R (8 bits): flat, one uint4 per thread ----------------
template <int R>
__global__ void k_radix() {
  __shared__ unsigned h[256];
  int t = threadIdx.x;
  h[t] = 0u;
  unsigned prefix = (R == 0) ? 0u : g_state.prefix;
  __syncthreads();
  const int SHIFT = 24 - 8 * R;
  int lane = t & 31;
  int i = blockIdx.x * blockDim.x + t;
  uint4 kk = make_uint4(0, 0, 0, 0);
  bool in = (i < N4);
  if (in) kk = ((const uint4*)g_keys)[i];
#pragma unroll
  for (int s = 0; s < 4; s++) {
    unsigned key = (&kk.x)[s];
    bool match;
    if constexpr (R == 0) match = in;
    else                  match = in && ((key >> (SHIFT + 8)) == prefix);
    unsigned bin = match ? ((key >> SHIFT) & 255u) : 0xFFFFFFFFu;
    unsigned peers = __match_any_sync(0xFFFFFFFFu, bin);
    if (lane == (__ffs(peers) - 1) && bin != 0xFFFFFFFFu)
      atomicAdd(&h[bin], (unsigned)__popc(peers));
  }
  __syncthreads();
  unsigned c = h[t];
  if (c) atomicAdd(&g_state.hist[R][t], c);
  __threadfence();
  __shared__ int s_last;
  if (t == 0)
    s_last = (atomicAdd(&g_state.done[R], 1u) == gridDim.x - 1) ? 1 : 0;
  __syncthreads();
  if (!s_last) return;
  h[t] = g_state.hist[R][t];
  __syncthreads();
  if (t == 0) {
    unsigned k = (R == 0) ? (unsigned)K_CAND : g_state.k;
    int b = 255;
    for (; b > 0; b--) {
      unsigned cc = h[b];
      if (k <= cc) break;
      k -= cc;
    }
    g_state.prefix = (prefix << 8) | (unsigned)b;
    g_state.k = k;
    if (R == 3) g_state.kth = (prefix << 8) | (unsigned)b;
  }
}

// ---------------- compact candidates with key >= kth (flat, uint4) ----------------
__global__ void k_compact() {
  unsigned kth = g_state.kth;
  int i = blockIdx.x * blockDim.x + threadIdx.x;
  if (i >= N4) return;
  uint4 kk = ((const uint4*)g_keys)[i];
#pragma unroll
  for (int s = 0; s < 4; s++) {
    unsigned key = (&kk.x)[s];
    if (key >= kth) {
      unsigned idx = (unsigned)(4 * i + s);
      unsigned pos = atomicAdd(&g_state.count, 1u);
      if (pos < CAP)
        g_cand[pos] = ((unsigned long long)key << 32) | (unsigned long long)(0xFFFFFFFFu - idx);
    }
  }
}

// ---------------- single-block bitonic sort (2048) + gather candidate SoA ----------------
__global__ void k_sort(const float* __restrict__ boxes) {
  __shared__ unsigned long long s[CAP];
  __shared__ unsigned s_n;
  if (threadIdx.x == 0) s_n = min(g_state.count, (unsigned)CAP);
  __syncthreads();
  unsigned n = s_n;
  for (int t = threadIdx.x; t < CAP; t += blockDim.x)
    s[t] = (t < (int)n) ? g_cand[t] : 0ull;
  __syncthreads();
  for (int k = 2; k <= CAP; k <<= 1) {
    for (int j = k >> 1; j > 0; j >>= 1) {
      for (int idx = threadIdx.x; idx < CAP; idx += blockDim.x) {
        int l = idx ^ j;
        if (l > idx) {
          unsigned long long a = s[idx], b = s[l];
          bool up = ((idx & k) == 0);  // ascending network
          if ((a > b) == up) { s[idx] = b; s[l] = a; }
        }
      }
      __syncthreads();
    }
  }
  int t = threadIdx.x;
  if (t < K_CAND) {
    unsigned long long e = s[CAP - 1 - t];  // rank t descending
    unsigned key = (unsigned)(e >> 32);
    unsigned idx = 0xFFFFFFFFu - (unsigned)e;
    const float4* b4 = (const float4*)boxes;
    float4 bb = b4[idx];
    g_cx1[t] = bb.x; g_cy1[t] = bb.y; g_cx2[t] = bb.z; g_cy2[t] = bb.w;
    g_cscore[t] = __uint_as_float(key);
    g_clabel[t] = (int)g_labels[idx];
  }
}

// ---------------- grid kernel: suppression bitmask matrix (offset boxes, j > i) ----------------
__global__ void k_iou() {
  __shared__ float sx1[K_CAND], sy1[K_CAND], sx2[K_CAND], sy2[K_CAND], sar[K_CAND];
  for (int t = threadIdx.x; t < K_CAND; t += blockDim.x) {
    float off = (float)g_clabel[t] * 4.0f;
    float x1 = g_cx1[t] + off, y1 = g_cy1[t] + off;
    float x2 = g_cx2[t] + off, y2 = g_cy2[t] + off;
    sx1[t] = x1; sy1[t] = y1; sx2[t] = x2; sy2[t] = y2;
    sar[t] = (x2 - x1) * (y2 - y1);  // area from offset coords, like reference
  }
  __syncthreads();
  int g = blockIdx.x * blockDim.x + threadIdx.x;
  if (g >= K_CAND * 32) return;
  int i = g >> 5;
  int w = g & 31;
  float x1 = sx1[i], y1 = sy1[i], x2 = sx2[i], y2 = sy2[i], ai = sar[i];
  unsigned word = 0u;
#pragma unroll
  for (int jj = 0; jj < 32; jj++) {
    int j = w * 32 + jj;
    if (j > i && j < K_CAND) {
      float xx1 = fmaxf(x1, sx1[j]);
      float yy1 = fmaxf(y1, sy1[j]);
      float xx2 = fminf(x2, sx2[j]);
      float yy2 = fminf(y2, sy2[j]);
      float inter = fmaxf(xx2 - xx1, 0.0f) * fmaxf(yy2 - yy1, 0.0f);
      float uni = fmaxf(ai + sar[j] - inter, 1e-9f);
      float iou = __fdiv_rn(inter, uni);
      if (iou > IOU_THR) word |= (1u << jj);
    }
  }
  g_sup[i * 32 + w] = word;
}

// ---------------- final: sequential greedy reduction (1 warp) + output write ----------------
__global__ void k_final(float* __restrict__ out) {
  extern __shared__ unsigned ssup[];  // 32000 words = 128000 B
  __shared__ unsigned skeep[32];
  for (int t = threadIdx.x; t < K_CAND * 32; t += blockDim.x)
    ssup[t] = g_sup[t];
  __syncthreads();

  if (threadIdx.x < 32) {
    int lane = threadIdx.x;
    unsigned kw = 0u;  // keep word for columns [32*lane, 32*lane+32)
#pragma unroll
    for (int jj = 0; jj < 32; jj++) {
      int j = lane * 32 + jj;
      bool v = (j < K_CAND) && (g_cscore[j] > SCORE_THR);
      if (v) kw |= (1u << jj);
    }
    for (int c = 0; c < 32; c++) {
      unsigned bkw = __shfl_sync(0xFFFFFFFFu, kw, c);  // current chunk's keep word, replicated
      int base = c * 32;
#pragma unroll
      for (int r = 0; r < 32; r++) {
        int i = base + r;
        if (i < K_CAND) {
          unsigned rowl = ssup[i * 32 + lane];  // conflict-free
          unsigned rowc = ssup[i * 32 + c];     // broadcast
          if (bkw & (1u << r)) {
            kw  &= ~rowl;
            bkw &= ~rowc;
          }
        }
      }
    }
    skeep[lane] = kw;
  }
  __syncthreads();

  int t = threadIdx.x;
  if (t < K_CAND) {
    bool keep = (skeep[t >> 5] >> (t & 31)) & 1u;
    float kf = keep ? 1.0f : 0.0f;
    out[t * 4 + 0] = g_cx1[t] * kf;
    out[t * 4 + 1] = g_cy1[t] * kf;
    out[t * 4 + 2] = g_cx2[t] * kf;
    out[t * 4 + 3] = g_cy2[t] * kf;
    out[4000 + t] = keep ? (float)(g_clabel[t] + 1) : 0.0f;
    out[5000 + t] = g_cscore[t] * kf;
    out[6000 + t] = kf;
  }
}

// ---------------- launch ----------------
extern "C" void kernel_launch(void* const* d_in, const int* in_sizes, int n_in,
                              void* d_out, int out_size) {
  const float* scores = (const float*)d_in[0];
  const float* boxes  = (const float*)d_in[1];
  float* out = (float*)d_out;

  cudaFuncSetAttribute(k_final, cudaFuncAttributeMaxDynamicSharedMemorySize, 128000);

  const int RB = (N4 + 255) / 256;  // 391 blocks, one uint4 per thread

  k_reduce<<<2048, 256>>>(scores);
  k_radix<0><<<RB, 256>>>();
  k_radix<1><<<RB, 256>>>();
  k_radix<2><<<RB, 256>>>();
  k_radix<3><<<RB, 256>>>();
  k_compact<<<RB, 256>>>();
  k_sort<<<1, 1024>>>(boxes);
  k_iou<<<125, 256>>>();
  k_final<<<1, 1024, 128000>>>(out);
}